// round 10
// baseline (speedup 1.0000x reference)
#include <cuda_runtime.h>
#include <cuda_bf16.h>
#include <cuda_pipeline.h>

// Problem constants
#define CDIM 512
#define NSEG 640         // S
#define PPP  250         // points per segment
#define NB   32          // BO
#define NERF 147         // 7 + 7*10*2

// Scratch (__device__ globals; allocation-free rule)
__device__ float g_ctr  [NSEG*3];
__device__ float g_nerf [NSEG*NERF];
__device__ float g_E32  [NB*CDIM];
__device__ float g_th   [NB*CDIM];
__device__ float g_temb [NB*CDIM];
__device__ float g_X    [NSEG*CDIM];
__device__ float g_Y1   [NSEG*256];
__device__ float g_Y2   [NSEG*128];
// BN stats: [0,256) sum1 | [256,512) sumsq1 | [512,640) sum2 | [640,768) sumsq2
__device__ float g_stats[768];

// Dynamic SMEM sizes (bytes)
#define SMEM_KX  ((147*128 + 16*148)*4)            // 84736
#define SMEM_G1  ((8*512 + 2*128*128)*4)           // 147456
#define SMEM_G2  ((256*128 + 8*256 + 512)*4)       // 141312

// ---------------------------------------------------------------------------
// K0 prep: blocks 0..639 -> segment mean + quat rotate + nerf row
//          blocks 640..643 -> raw timestep embedding; block 640 zeros stats
// ---------------------------------------------------------------------------
__global__ void k_pre(const float* __restrict__ noise,
                      const int*   __restrict__ ts,
                      const float* __restrict__ pcs,
                      const int*   __restrict__ blen)
{
    int bid = blockIdx.x, tid = threadIdx.x;
    if (bid < NSEG) {
        __shared__ float sh[192];
        __shared__ float shn[8];
        int s = bid;
        if (tid < 7) shn[tid] = noise[s*7 + tid];
        const float* base = pcs + (long)s * (PPP*3);
        float a = 0.f;
        for (int j = tid; j < PPP*3; j += 192) a += base[j];
        sh[tid] = a;
        __syncthreads();
        if (tid < 3) {
            float m = 0.f;
            for (int k = tid; k < 192; k += 3) m += sh[k];
            sh[tid] = m;
        }
        __syncthreads();
        if (tid == 0) {
            float inv = 1.f / (float)blen[s];
            float px = sh[0]*inv, py = sh[1]*inv, pz = sh[2]*inv;
            float qw = shn[3], qx = shn[4], qy = shn[5], qz = shn[6];
            float rn = rsqrtf(qw*qw + qx*qx + qy*qy + qz*qz);
            qw*=rn; qx*=rn; qy*=rn; qz*=rn;
            float tx = 2.f*(qy*pz - qz*py);
            float ty = 2.f*(qz*px - qx*pz);
            float tz = 2.f*(qx*py - qy*px);
            g_ctr[s*3+0] = px + qw*tx + (qy*tz - qz*ty) + shn[0];
            g_ctr[s*3+1] = py + qw*ty + (qz*tx - qx*tz) + shn[1];
            g_ctr[s*3+2] = pz + qw*tz + (qx*ty - qy*tx) + shn[2];
        }
        if (tid < NERF) {
            float v;
            if (tid < 7) v = shn[tid];
            else {
                int jj = tid - 7;
                int f  = jj / 14;
                int rr = jj - f*14;
                float x = shn[rr < 7 ? rr : rr-7];
                float arg = x * (float)(1 << f);
                v = (rr < 7) ? sinf(arg) : cosf(arg);
            }
            g_nerf[s*NERF + tid] = v;
        }
    } else {
        int b2 = bid - NSEG;
        for (int idx = tid; idx < 8*CDIM; idx += 192) {
            int r = idx >> 9, k = idx & 511;
            float t = (float)ts[b2*8 + r];
            int j = k & 255;
            float f = expf(-9.210340371976184f * (float)j * (1.0f/256.0f));
            float a = t * f;
            g_E32[(b2*8 + r)*CDIM + k] = (k < 256) ? cosf(a) : sinf(a);
        }
        if (b2 == 0)
            for (int i = tid; i < 768; i += 192) g_stats[i] = 0.f;
    }
}

// ---------------------------------------------------------------------------
// 32x512 @ 512x512 MLP. grid (4,16), block 256: 8 rows x 32 cols,
// K=512 split 8 ways. STAGE 0: g_E32 -> silu -> g_th.  STAGE 1: g_th -> g_temb.
// ---------------------------------------------------------------------------
template<int STAGE>
__global__ void k_mlp512(const float* __restrict__ W,
                         const float* __restrict__ B)
{
    const float* Ein = (STAGE == 0) ? g_E32 : g_th;
    float*       Out = (STAGE == 0) ? g_th  : g_temb;
    __shared__ float Es[8][CDIM];
    __shared__ float ps[7][8][32];
    int tid = threadIdx.x;
    int lane = tid & 31, ks = tid >> 5;
    int r0 = blockIdx.x * 8;
    int c  = blockIdx.y * 32 + lane;
    for (int idx = tid; idx < 8*128; idx += 256) {
        int r = idx >> 7, q = idx & 127;
        ((float4*)Es[r])[q] = ((const float4*)(Ein + (r0+r)*CDIM))[q];
    }
    __syncthreads();
    int kbase = ks * 64;
    const float* Wp = W + (long)kbase * CDIM + c;
    float acc[8];
    #pragma unroll
    for (int r = 0; r < 8; r++) acc[r] = 0.f;
    for (int k0 = 0; k0 < 64; k0 += 8) {
        float w[8];
        #pragma unroll
        for (int u = 0; u < 8; u++) w[u] = Wp[(long)(k0+u)*CDIM];
        #pragma unroll
        for (int r = 0; r < 8; r++) {
            float4 e0 = *(const float4*)&Es[r][kbase + k0];
            float4 e1 = *(const float4*)&Es[r][kbase + k0 + 4];
            acc[r] = fmaf(e0.x, w[0], acc[r]);
            acc[r] = fmaf(e0.y, w[1], acc[r]);
            acc[r] = fmaf(e0.z, w[2], acc[r]);
            acc[r] = fmaf(e0.w, w[3], acc[r]);
            acc[r] = fmaf(e1.x, w[4], acc[r]);
            acc[r] = fmaf(e1.y, w[5], acc[r]);
            acc[r] = fmaf(e1.z, w[6], acc[r]);
            acc[r] = fmaf(e1.w, w[7], acc[r]);
        }
    }
    if (ks > 0) {
        #pragma unroll
        for (int r = 0; r < 8; r++) ps[ks-1][r][lane] = acc[r];
    }
    __syncthreads();
    if (ks == 0) {
        float bb = B[c];
        #pragma unroll
        for (int r = 0; r < 8; r++) {
            float v = acc[r] + bb;
            #pragma unroll
            for (int u = 0; u < 7; u++) v += ps[u][r][lane];
            if (STAGE == 0) v = v / (1.f + expf(-v));
            Out[(r0+r)*CDIM + c] = v;
        }
    }
}

// ---------------------------------------------------------------------------
// K3: X = nerf @ pfc_w + pfc_b + ctr.pe_w + pe_b + temb[s/20]
// grid (40,4), block 256. Weights (147x128 slice, 75KB) cp.async-staged in
// SMEM; each thread computes 8 rows x 1 col with full K from SMEM only.
// ---------------------------------------------------------------------------
__global__ void k_X(const float* __restrict__ PFW, const float* __restrict__ PFB,
                    const float* __restrict__ PEW, const float* __restrict__ PEB)
{
    extern __shared__ float sm[];
    float* Ws = sm;                    // [147][128]
    float* En = sm + 147*128;          // [16][148]
    int tid = threadIdx.x;
    int cl = tid & 127, rh = tid >> 7;       // col-in-block, row-half
    int r0 = blockIdx.x * 16;
    int cb = blockIdx.y;
    int c  = cb * 128 + cl;

    // async-stage weight slice: 147 rows x 32 float4
    for (int i = tid; i < 147*32; i += 256) {
        int k = i >> 5, q = i & 31;
        __pipeline_memcpy_async(Ws + k*128 + q*4,
                                PFW + (long)k*CDIM + cb*128 + q*4, 16);
    }
    __pipeline_commit();
    // nerf rows via regular loads (overlap with async copies)
    for (int idx = tid; idx < 16*NERF; idx += 256) {
        int r = idx / NERF, j = idx - r*NERF;
        En[r*148 + j] = g_nerf[(r0+r)*NERF + j];
    }
    __pipeline_wait_prior(0);
    __syncthreads();

    float acc[8];
    #pragma unroll
    for (int r = 0; r < 8; r++) acc[r] = 0.f;
    const float* Erow = En + (rh*8)*148;
    for (int k0 = 0; k0 < 144; k0 += 8) {
        float w[8];
        #pragma unroll
        for (int u = 0; u < 8; u++) w[u] = Ws[(k0+u)*128 + cl];
        #pragma unroll
        for (int r = 0; r < 8; r++) {
            const float* e = Erow + r*148 + k0;
            float4 e0 = *(const float4*)e;
            float4 e1 = *(const float4*)(e+4);
            acc[r] = fmaf(e0.x, w[0], acc[r]);
            acc[r] = fmaf(e0.y, w[1], acc[r]);
            acc[r] = fmaf(e0.z, w[2], acc[r]);
            acc[r] = fmaf(e0.w, w[3], acc[r]);
            acc[r] = fmaf(e1.x, w[4], acc[r]);
            acc[r] = fmaf(e1.y, w[5], acc[r]);
            acc[r] = fmaf(e1.z, w[6], acc[r]);
            acc[r] = fmaf(e1.w, w[7], acc[r]);
        }
    }
    {   // tail k = 144..146
        float w0 = Ws[144*128 + cl], w1 = Ws[145*128 + cl], w2 = Ws[146*128 + cl];
        #pragma unroll
        for (int r = 0; r < 8; r++) {
            const float* e = Erow + r*148;
            acc[r] = fmaf(e[144], w0, acc[r]);
            acc[r] = fmaf(e[145], w1, acc[r]);
            acc[r] = fmaf(e[146], w2, acc[r]);
        }
    }
    float pw0 = PEW[c], pw1 = PEW[CDIM + c], pw2 = PEW[2*CDIM + c];
    float pb  = PEB[c] + PFB[c];
    #pragma unroll
    for (int r = 0; r < 8; r++) {
        int s = r0 + rh*8 + r;
        float v = acc[r] + pb
                + g_ctr[s*3+0]*pw0 + g_ctr[s*3+1]*pw1 + g_ctr[s*3+2]*pw2
                + g_temb[(s/20)*CDIM + c];
        g_X[s*CDIM + c] = v;
    }
}

// ---------------------------------------------------------------------------
// K4: Y1 = X @ o_w1 + o_b1 (640x512x256) + stat atomics.
// grid (80,2), block 256: 8 rows x 128 cols. K=512 streamed as 4x64KB
// double-buffered cp.async chunks; compute fully from SMEM.
// ---------------------------------------------------------------------------
__global__ void k_gemm1(const float* __restrict__ W, const float* __restrict__ B)
{
    extern __shared__ float sm[];
    float* Xs = sm;                    // [8][512]
    float* Wb = sm + 8*512;            // 2 x [128][128]
    int tid = threadIdx.x;
    int cl = tid & 127, rh = tid >> 7;
    int r0 = blockIdx.x * 8;
    int cb = blockIdx.y;
    const float* Wslice = W + cb*128;  // row stride 256

    // stage X rows (contiguous 4096 floats) + chunk 0, one commit group
    for (int i = tid; i < 1024; i += 256)
        __pipeline_memcpy_async(Xs + i*4, g_X + (long)r0*CDIM + i*4, 16);
    for (int i = tid; i < 4096; i += 256) {
        int k = i >> 5, q = i & 31;
        __pipeline_memcpy_async(Wb + k*128 + q*4,
                                Wslice + (long)k*256 + q*4, 16);
    }
    __pipeline_commit();

    float acc[4] = {0.f, 0.f, 0.f, 0.f};
    for (int cc = 0; cc < 4; cc++) {
        if (cc < 3) {
            float* dst = Wb + ((cc+1)&1)*16384;
            for (int i = tid; i < 4096; i += 256) {
                int k = i >> 5, q = i & 31;
                __pipeline_memcpy_async(dst + k*128 + q*4,
                                        Wslice + (long)((cc+1)*128 + k)*256 + q*4, 16);
            }
            __pipeline_commit();
            __pipeline_wait_prior(1);
        } else {
            __pipeline_wait_prior(0);
        }
        __syncthreads();
        const float* Wc = Wb + (cc&1)*16384;
        for (int k0 = 0; k0 < 128; k0 += 8) {
            float w[8];
            #pragma unroll
            for (int u = 0; u < 8; u++) w[u] = Wc[(k0+u)*128 + cl];
            #pragma unroll
            for (int r = 0; r < 4; r++) {
                const float* e = Xs + (rh*4 + r)*CDIM + cc*128 + k0;
                float4 e0 = *(const float4*)e;
                float4 e1 = *(const float4*)(e+4);
                acc[r] = fmaf(e0.x, w[0], acc[r]);
                acc[r] = fmaf(e0.y, w[1], acc[r]);
                acc[r] = fmaf(e0.z, w[2], acc[r]);
                acc[r] = fmaf(e0.w, w[3], acc[r]);
                acc[r] = fmaf(e1.x, w[4], acc[r]);
                acc[r] = fmaf(e1.y, w[5], acc[r]);
                acc[r] = fmaf(e1.z, w[6], acc[r]);
                acc[r] = fmaf(e1.w, w[7], acc[r]);
            }
        }
        __syncthreads();
    }
    float bb = B[cb*128 + cl];
    float s1 = 0.f, s2 = 0.f;
    #pragma unroll
    for (int r = 0; r < 4; r++) {
        float y = acc[r] + bb;
        g_Y1[(r0 + rh*4 + r)*256 + cb*128 + cl] = y;
        s1 += y; s2 += y*y;
    }
    atomicAdd(&g_stats[cb*128 + cl], s1);
    atomicAdd(&g_stats[256 + cb*128 + cl], s2);
}

// ---------------------------------------------------------------------------
// K5: H1 = relu(bn1(Y1)); Y2 = H1 @ o_w2 + o_b2 + stat atomics.
// grid (80), block 256: 8 rows x 128 cols. Full 128KB W2 cp.async-staged,
// overlapped with BN transform of Y1 into SMEM.
// ---------------------------------------------------------------------------
__global__ void k_gemm2(const float* __restrict__ W, const float* __restrict__ B,
                        const float* __restrict__ G1, const float* __restrict__ B1)
{
    extern __shared__ float sm[];
    float* W2s = sm;                   // [256][128]
    float* Hs  = sm + 256*128;         // [8][256]
    float* scp = sm + 256*128 + 8*256; // [256]
    float* sbp = scp + 256;            // [256]
    int tid = threadIdx.x;
    int cl = tid & 127, rh = tid >> 7;
    int r0 = blockIdx.x * 8;

    for (int i = tid; i < 8192; i += 256)
        __pipeline_memcpy_async(W2s + i*4, W + i*4, 16);
    __pipeline_commit();

    {
        float m = g_stats[tid]       * (1.f/NSEG);
        float v = g_stats[256 + tid] * (1.f/NSEG) - m*m;
        float s = rsqrtf(v + 1e-5f) * G1[tid];
        scp[tid] = s; sbp[tid] = B1[tid] - m*s;
    }
    __syncthreads();
    for (int idx = tid; idx < 8*256; idx += 256) {
        int r = idx >> 8, j = idx & 255;
        float y = g_Y1[(r0+r)*256 + j];
        Hs[idx] = fmaxf(fmaf(y, scp[j], sbp[j]), 0.f);
    }
    __pipeline_wait_prior(0);
    __syncthreads();

    float acc[4] = {0.f, 0.f, 0.f, 0.f};
    for (int k0 = 0; k0 < 256; k0 += 8) {
        float w[8];
        #pragma unroll
        for (int u = 0; u < 8; u++) w[u] = W2s[(k0+u)*128 + cl];
        #pragma unroll
        for (int r = 0; r < 4; r++) {
            const float* e = Hs + (rh*4 + r)*256 + k0;
            float4 e0 = *(const float4*)e;
            float4 e1 = *(const float4*)(e+4);
            acc[r] = fmaf(e0.x, w[0], acc[r]);
            acc[r] = fmaf(e0.y, w[1], acc[r]);
            acc[r] = fmaf(e0.z, w[2], acc[r]);
            acc[r] = fmaf(e0.w, w[3], acc[r]);
            acc[r] = fmaf(e1.x, w[4], acc[r]);
            acc[r] = fmaf(e1.y, w[5], acc[r]);
            acc[r] = fmaf(e1.z, w[6], acc[r]);
            acc[r] = fmaf(e1.w, w[7], acc[r]);
        }
    }
    float bb = B[cl];
    float s1 = 0.f, s2 = 0.f;
    #pragma unroll
    for (int r = 0; r < 4; r++) {
        float y = acc[r] + bb;
        g_Y2[(r0 + rh*4 + r)*128 + cl] = y;
        s1 += y; s2 += y*y;
    }
    atomicAdd(&g_stats[512 + cl], s1);
    atomicAdd(&g_stats[640 + cl], s2);
}

// ---------------------------------------------------------------------------
// K6: out = relu(bn2(Y2)) @ o_w3 + o_b3.  grid (80), block 256.
// ---------------------------------------------------------------------------
__global__ void k_out(const float* __restrict__ W3, const float* __restrict__ B3,
                      const float* __restrict__ G2, const float* __restrict__ B2c,
                      float* __restrict__ out)
{
    __shared__ float sc[128], sb[128];
    __shared__ float h[8][128];
    __shared__ float w3[128*7];
    __shared__ float b3[7];
    int tid = threadIdx.x;
    if (tid < 128) {
        float m = g_stats[512 + tid] * (1.f/NSEG);
        float v = g_stats[640 + tid] * (1.f/NSEG) - m*m;
        float s = rsqrtf(v + 1e-5f) * G2[tid];
        sc[tid] = s; sb[tid] = B2c[tid] - m*s;
    }
    for (int idx = tid; idx < 128*7; idx += 256) w3[idx] = W3[idx];
    if (tid < 7) b3[tid] = B3[tid];
    __syncthreads();
    int r0 = blockIdx.x * 8;
    for (int idx = tid; idx < 8*128; idx += 256) {
        int r = idx >> 7, j = idx & 127;
        float y = g_Y2[(r0+r)*128 + j];
        h[r][j] = fmaxf(fmaf(y, sc[j], sb[j]), 0.f);
    }
    __syncthreads();
    int wid = tid >> 5, lane = tid & 31;
    float hv[4];
    #pragma unroll
    for (int u = 0; u < 4; u++) hv[u] = h[wid][lane + u*32];
    #pragma unroll
    for (int j = 0; j < 7; j++) {
        float a = 0.f;
        #pragma unroll
        for (int u = 0; u < 4; u++) a = fmaf(hv[u], w3[(lane + u*32)*7 + j], a);
        #pragma unroll
        for (int o = 16; o; o >>= 1) a += __shfl_down_sync(0xffffffffu, a, o);
        if (lane == 0) out[(r0+wid)*7 + j] = a + b3[j];
    }
}

// ---------------------------------------------------------------------------
extern "C" void kernel_launch(void* const* d_in, const int* in_sizes, int n_in,
                              void* d_out, int out_size)
{
    const float* noise = (const float*)d_in[0];
    const int*   ts    = (const int*)  d_in[1];
    const float* pcs   = (const float*)d_in[2];
    const int*   blen  = (const int*)  d_in[4];
    const float* pew   = (const float*)d_in[5];
    const float* peb   = (const float*)d_in[6];
    const float* tw1   = (const float*)d_in[7];
    const float* tb1   = (const float*)d_in[8];
    const float* tw2   = (const float*)d_in[9];
    const float* tb2   = (const float*)d_in[10];
    const float* pfw   = (const float*)d_in[11];
    const float* pfb   = (const float*)d_in[12];
    const float* ow1   = (const float*)d_in[13];
    const float* ob1   = (const float*)d_in[14];
    const float* bn1g  = (const float*)d_in[15];
    const float* bn1b  = (const float*)d_in[16];
    const float* ow2   = (const float*)d_in[17];
    const float* ob2   = (const float*)d_in[18];
    const float* bn2g  = (const float*)d_in[19];
    const float* bn2b  = (const float*)d_in[20];
    const float* ow3   = (const float*)d_in[21];
    const float* ob3   = (const float*)d_in[22];
    float* out = (float*)d_out;

    cudaFuncSetAttribute(k_X,     cudaFuncAttributeMaxDynamicSharedMemorySize, SMEM_KX);
    cudaFuncSetAttribute(k_gemm1, cudaFuncAttributeMaxDynamicSharedMemorySize, SMEM_G1);
    cudaFuncSetAttribute(k_gemm2, cudaFuncAttributeMaxDynamicSharedMemorySize, SMEM_G2);

    k_pre       <<<NSEG + 4, 192>>>(noise, ts, pcs, blen);
    k_mlp512<0> <<<dim3(4,16), 256>>>(tw1, tb1);
    k_mlp512<1> <<<dim3(4,16), 256>>>(tw2, tb2);
    k_X         <<<dim3(40,4), 256, SMEM_KX>>>(pfw, pfb, pew, peb);
    k_gemm1     <<<dim3(80,2), 256, SMEM_G1>>>(ow1, ob1);
    k_gemm2     <<<80, 256, SMEM_G2>>>(ow2, ob2, bn1g, bn1b);
    k_out       <<<80, 256>>>(ow3, ob3, bn2g, bn2b, out);
}

// round 11
// speedup vs baseline: 1.0745x; 1.0745x over previous
#include <cuda_runtime.h>
#include <cuda_bf16.h>

// Problem constants
#define CDIM 512
#define NSEG 640         // S
#define PPP  250         // points per segment
#define NB   32          // BO
#define NERF 147         // 7 + 7*10*2
#define NBLK 296         // persistent grid: 2 blocks/SM on 148 SMs

// Scratch (__device__ globals; allocation-free rule)
__device__ float g_ctr  [NSEG*3];
__device__ float g_nerf [NSEG*NERF];
__device__ float g_E32  [NB*CDIM];
__device__ float g_th   [NB*CDIM];
__device__ float g_temb [NB*CDIM];
__device__ float g_X    [NSEG*CDIM];
__device__ float g_Y1   [NSEG*256];
__device__ float g_Y2   [NSEG*128];
// BN stats: [0,256) sum1 | [256,512) sumsq1 | [512,640) sum2 | [640,768) sumsq2
__device__ float g_stats[768];

// Grid barrier state (CG-style; gen is monotonic across launches)
__device__ unsigned int g_bar_count = 0;
__device__ volatile unsigned int g_bar_gen = 0;

__device__ __forceinline__ void gbar()
{
    __syncthreads();
    if (threadIdx.x == 0) {
        __threadfence();
        unsigned int gen = g_bar_gen;
        if (atomicAdd(&g_bar_count, 1) == NBLK - 1) {
            atomicExch(&g_bar_count, 0);
            __threadfence();
            g_bar_gen = gen + 1;
        } else {
            while (g_bar_gen == gen) __nanosleep(64);
        }
        __threadfence();
    }
    __syncthreads();
}

// ---------------------------------------------------------------------------
// The megakernel: 7 phases, identical math to the R9 7-kernel chain.
// Static SMEM union: 6144 floats = 24 KB.
// ---------------------------------------------------------------------------
__global__ void __launch_bounds__(256, 2)
mega(const float* __restrict__ noise, const int* __restrict__ ts,
     const float* __restrict__ pcs,   const int* __restrict__ blen,
     const float* __restrict__ pew,   const float* __restrict__ peb,
     const float* __restrict__ tw1,   const float* __restrict__ tb1,
     const float* __restrict__ tw2,   const float* __restrict__ tb2,
     const float* __restrict__ pfw,   const float* __restrict__ pfb,
     const float* __restrict__ ow1,   const float* __restrict__ ob1,
     const float* __restrict__ bn1g,  const float* __restrict__ bn1b,
     const float* __restrict__ ow2,   const float* __restrict__ ob2,
     const float* __restrict__ bn2g,  const float* __restrict__ bn2b,
     const float* __restrict__ ow3,   const float* __restrict__ ob3,
     float* __restrict__ out)
{
    __shared__ float sm[6144];
    int tid = threadIdx.x;
    int lane = tid & 31;

    // ===== Phase 0: prep =====================================================
    for (int item = blockIdx.x; item < NSEG + 4; item += NBLK) {
        if (item < NSEG) {
            int s = item;
            if (tid < 7) sm[768 + tid] = noise[s*7 + tid];
            float a0 = 0.f, a1 = 0.f, a2 = 0.f;
            const float* base = pcs + (long)s * (PPP*3);
            for (int j = tid; j < PPP*3; j += 256) {
                float v = base[j];
                int cph = j - (j/3)*3;
                if (cph == 0) a0 += v; else if (cph == 1) a1 += v; else a2 += v;
            }
            sm[tid] = a0; sm[256 + tid] = a1; sm[512 + tid] = a2;
            __syncthreads();
            if (tid < 3) {
                float m = 0.f;
                const float* p = sm + tid*256;
                for (int k = 0; k < 256; k++) m += p[k];
                sm[960 + tid] = m;
            }
            __syncthreads();
            if (tid == 0) {
                float inv = 1.f / (float)blen[s];
                float px = sm[960]*inv, py = sm[961]*inv, pz = sm[962]*inv;
                float qw = sm[768+3], qx = sm[768+4], qy = sm[768+5], qz = sm[768+6];
                float rn = rsqrtf(qw*qw + qx*qx + qy*qy + qz*qz);
                qw*=rn; qx*=rn; qy*=rn; qz*=rn;
                float tx = 2.f*(qy*pz - qz*py);
                float ty = 2.f*(qz*px - qx*pz);
                float tz = 2.f*(qx*py - qy*px);
                g_ctr[s*3+0] = px + qw*tx + (qy*tz - qz*ty) + sm[768+0];
                g_ctr[s*3+1] = py + qw*ty + (qz*tx - qx*tz) + sm[768+1];
                g_ctr[s*3+2] = pz + qw*tz + (qx*ty - qy*tx) + sm[768+2];
            }
            if (tid < NERF) {
                float v;
                if (tid < 7) v = sm[768 + tid];
                else {
                    int jj = tid - 7;
                    int f  = jj / 14;
                    int rr = jj - f*14;
                    float x = sm[768 + (rr < 7 ? rr : rr-7)];
                    float arg = x * (float)(1 << f);
                    v = (rr < 7) ? sinf(arg) : cosf(arg);
                }
                g_nerf[s*NERF + tid] = v;
            }
            __syncthreads();
        } else {
            int b2 = item - NSEG;
            for (int idx = tid; idx < 8*CDIM; idx += 256) {
                int r = idx >> 9, k = idx & 511;
                float t = (float)ts[b2*8 + r];
                int j = k & 255;
                float f = expf(-9.210340371976184f * (float)j * (1.0f/256.0f));
                float a = t * f;
                g_E32[(b2*8 + r)*CDIM + k] = (k < 256) ? cosf(a) : sinf(a);
            }
            if (b2 == 0)
                for (int i = tid; i < 768; i += 256) g_stats[i] = 0.f;
        }
    }
    gbar();

    // ===== Phases 1 & 2: timestep MLP (two 32x512x512 layers) ================
    #pragma unroll 1
    for (int stage = 0; stage < 2; stage++) {
        const float* Ein = (stage == 0) ? g_E32 : g_th;
        float*       Out = (stage == 0) ? g_th  : g_temb;
        const float* W   = (stage == 0) ? tw1 : tw2;
        const float* B   = (stage == 0) ? tb1 : tb2;
        float* Es = sm;            // [8][512]
        float* ps = sm + 4096;     // [7][8][32]
        int ks = tid >> 5;
        for (int t = blockIdx.x; t < 64; t += NBLK) {
            int r0 = (t & 3) * 8;
            int c  = (t >> 2) * 32 + lane;
            for (int idx = tid; idx < 8*128; idx += 256) {
                int r = idx >> 7, q = idx & 127;
                ((float4*)(Es + r*CDIM))[q] = ((const float4*)(Ein + (r0+r)*CDIM))[q];
            }
            __syncthreads();
            int kbase = ks * 64;
            const float* Wp = W + (long)kbase * CDIM + c;
            float acc[8];
            #pragma unroll
            for (int r = 0; r < 8; r++) acc[r] = 0.f;
            for (int k0 = 0; k0 < 64; k0 += 8) {
                float w[8];
                #pragma unroll
                for (int u = 0; u < 8; u++) w[u] = Wp[(long)(k0+u)*CDIM];
                #pragma unroll
                for (int r = 0; r < 8; r++) {
                    const float* e = Es + r*CDIM + kbase + k0;
                    float4 e0 = *(const float4*)e;
                    float4 e1 = *(const float4*)(e+4);
                    acc[r] = fmaf(e0.x, w[0], acc[r]);
                    acc[r] = fmaf(e0.y, w[1], acc[r]);
                    acc[r] = fmaf(e0.z, w[2], acc[r]);
                    acc[r] = fmaf(e0.w, w[3], acc[r]);
                    acc[r] = fmaf(e1.x, w[4], acc[r]);
                    acc[r] = fmaf(e1.y, w[5], acc[r]);
                    acc[r] = fmaf(e1.z, w[6], acc[r]);
                    acc[r] = fmaf(e1.w, w[7], acc[r]);
                }
            }
            if (ks > 0) {
                #pragma unroll
                for (int r = 0; r < 8; r++) ps[(ks-1)*256 + r*32 + lane] = acc[r];
            }
            __syncthreads();
            if (ks == 0) {
                float bb = B[c];
                #pragma unroll
                for (int r = 0; r < 8; r++) {
                    float v = acc[r] + bb;
                    #pragma unroll
                    for (int u = 0; u < 7; u++) v += ps[u*256 + r*32 + lane];
                    if (stage == 0) v = v / (1.f + expf(-v));
                    Out[(r0+r)*CDIM + c] = v;
                }
            }
            __syncthreads();
        }
        gbar();
    }

    // ===== Phase 3: X = nerf @ pfc_w + ctr.pe_w + pe_b + pfc_b + temb ========
    {
        float* En  = sm;            // [8][148]
        float* red = sm + 1200;     // [8][128]
        int cl = tid & 127, ks = tid >> 7;
        for (int t = blockIdx.x; t < 320; t += NBLK) {
            int r0 = (t >> 2) * 8;
            int c  = (t & 3) * 128 + cl;
            for (int idx = tid; idx < 8*NERF; idx += 256) {
                int r = idx / NERF, j = idx - r*NERF;
                En[r*148 + j] = g_nerf[(r0+r)*NERF + j];
            }
            __syncthreads();
            float acc[8];
            #pragma unroll
            for (int r = 0; r < 8; r++) acc[r] = 0.f;
            const float* Wp = pfw + c;
            int kbeg = ks ? 72 : 0;
            int kend = ks ? 144 : 72;
            for (int k0 = kbeg; k0 < kend; k0 += 8) {
                float w[8];
                #pragma unroll
                for (int u = 0; u < 8; u++) w[u] = Wp[(k0+u)*CDIM];
                #pragma unroll
                for (int r = 0; r < 8; r++) {
                    const float* e = En + r*148 + k0;
                    float4 e0 = *(const float4*)e;
                    float4 e1 = *(const float4*)(e+4);
                    acc[r] = fmaf(e0.x, w[0], acc[r]);
                    acc[r] = fmaf(e0.y, w[1], acc[r]);
                    acc[r] = fmaf(e0.z, w[2], acc[r]);
                    acc[r] = fmaf(e0.w, w[3], acc[r]);
                    acc[r] = fmaf(e1.x, w[4], acc[r]);
                    acc[r] = fmaf(e1.y, w[5], acc[r]);
                    acc[r] = fmaf(e1.z, w[6], acc[r]);
                    acc[r] = fmaf(e1.w, w[7], acc[r]);
                }
            }
            if (ks == 1) {
                float w0 = Wp[144*CDIM], w1 = Wp[145*CDIM], w2 = Wp[146*CDIM];
                #pragma unroll
                for (int r = 0; r < 8; r++) {
                    const float* e = En + r*148;
                    acc[r] = fmaf(e[144], w0, acc[r]);
                    acc[r] = fmaf(e[145], w1, acc[r]);
                    acc[r] = fmaf(e[146], w2, acc[r]);
                }
                #pragma unroll
                for (int r = 0; r < 8; r++) red[r*128 + cl] = acc[r];
            }
            __syncthreads();
            if (ks == 0) {
                float pw0 = pew[c], pw1 = pew[CDIM + c], pw2 = pew[2*CDIM + c];
                float pb  = peb[c] + pfb[c];
                #pragma unroll
                for (int r = 0; r < 8; r++) {
                    int s = r0 + r;
                    float v = acc[r] + red[r*128 + cl] + pb
                            + g_ctr[s*3+0]*pw0 + g_ctr[s*3+1]*pw1 + g_ctr[s*3+2]*pw2
                            + g_temb[(s/20)*CDIM + c];
                    g_X[s*CDIM + c] = v;
                }
            }
            __syncthreads();
        }
    }
    gbar();

    // ===== Phase 4: Y1 = X @ o_w1 + o_b1 + stats =============================
    {
        float* Xs  = sm;            // [8][512]
        float* red = sm + 4096;     // [8][128]
        int cl = tid & 127, ks = tid >> 7;
        for (int t = blockIdx.x; t < 160; t += NBLK) {
            int r0 = (t >> 1) * 8;
            int c  = (t & 1) * 128 + cl;
            for (int idx = tid; idx < 8*128; idx += 256) {
                int r = idx >> 7, q = idx & 127;
                ((float4*)(Xs + r*CDIM))[q] = ((const float4*)(g_X + (long)(r0+r)*CDIM))[q];
            }
            __syncthreads();
            int kbase = ks * 256;
            const float* Wp = ow1 + (long)kbase * 256 + c;
            float acc[8];
            #pragma unroll
            for (int r = 0; r < 8; r++) acc[r] = 0.f;
            for (int k0 = 0; k0 < 256; k0 += 8) {
                float w[8];
                #pragma unroll
                for (int u = 0; u < 8; u++) w[u] = Wp[(long)(k0+u)*256];
                #pragma unroll
                for (int r = 0; r < 8; r++) {
                    const float* e = Xs + r*CDIM + kbase + k0;
                    float4 e0 = *(const float4*)e;
                    float4 e1 = *(const float4*)(e+4);
                    acc[r] = fmaf(e0.x, w[0], acc[r]);
                    acc[r] = fmaf(e0.y, w[1], acc[r]);
                    acc[r] = fmaf(e0.z, w[2], acc[r]);
                    acc[r] = fmaf(e0.w, w[3], acc[r]);
                    acc[r] = fmaf(e1.x, w[4], acc[r]);
                    acc[r] = fmaf(e1.y, w[5], acc[r]);
                    acc[r] = fmaf(e1.z, w[6], acc[r]);
                    acc[r] = fmaf(e1.w, w[7], acc[r]);
                }
            }
            if (ks == 1) {
                #pragma unroll
                for (int r = 0; r < 8; r++) red[r*128 + cl] = acc[r];
            }
            __syncthreads();
            if (ks == 0) {
                float bb = ob1[c];
                float s1 = 0.f, s2 = 0.f;
                #pragma unroll
                for (int r = 0; r < 8; r++) {
                    float y = acc[r] + red[r*128 + cl] + bb;
                    g_Y1[(r0+r)*256 + c] = y;
                    s1 += y; s2 += y*y;
                }
                atomicAdd(&g_stats[c], s1);
                atomicAdd(&g_stats[256 + c], s2);
            }
            __syncthreads();
        }
    }
    gbar();

    // ===== Phase 5: H1 = relu(bn1(Y1)); Y2 = H1 @ o_w2 + o_b2 + stats ========
    {
        float* scp = sm;            // [256]
        float* sbp = sm + 256;      // [256]
        float* Hs  = sm + 512;      // [8][256]
        float* red = sm + 2560;     // [8][128]
        int cl = tid & 127, ks = tid >> 7;
        for (int t = blockIdx.x; t < 80; t += NBLK) {
            int r0 = t * 8;
            {
                float m = g_stats[tid]       * (1.f/NSEG);
                float v = g_stats[256 + tid] * (1.f/NSEG) - m*m;
                float s = rsqrtf(v + 1e-5f) * bn1g[tid];
                scp[tid] = s; sbp[tid] = bn1b[tid] - m*s;
            }
            __syncthreads();
            for (int idx = tid; idx < 8*256; idx += 256) {
                int r = idx >> 8, j = idx & 255;
                float y = g_Y1[(r0+r)*256 + j];
                Hs[idx] = fmaxf(fmaf(y, scp[j], sbp[j]), 0.f);
            }
            __syncthreads();
            int kbase = ks * 128;
            const float* Wp = ow2 + (long)kbase * 128 + cl;
            float acc[8];
            #pragma unroll
            for (int r = 0; r < 8; r++) acc[r] = 0.f;
            for (int k0 = 0; k0 < 128; k0 += 8) {
                float w[8];
                #pragma unroll
                for (int u = 0; u < 8; u++) w[u] = Wp[(long)(k0+u)*128];
                #pragma unroll
                for (int r = 0; r < 8; r++) {
                    const float* e = Hs + r*256 + kbase + k0;
                    float4 e0 = *(const float4*)e;
                    float4 e1 = *(const float4*)(e+4);
                    acc[r] = fmaf(e0.x, w[0], acc[r]);
                    acc[r] = fmaf(e0.y, w[1], acc[r]);
                    acc[r] = fmaf(e0.z, w[2], acc[r]);
                    acc[r] = fmaf(e0.w, w[3], acc[r]);
                    acc[r] = fmaf(e1.x, w[4], acc[r]);
                    acc[r] = fmaf(e1.y, w[5], acc[r]);
                    acc[r] = fmaf(e1.z, w[6], acc[r]);
                    acc[r] = fmaf(e1.w, w[7], acc[r]);
                }
            }
            if (ks == 1) {
                #pragma unroll
                for (int r = 0; r < 8; r++) red[r*128 + cl] = acc[r];
            }
            __syncthreads();
            if (ks == 0) {
                float bb = ob2[cl];
                float s1 = 0.f, s2 = 0.f;
                #pragma unroll
                for (int r = 0; r < 8; r++) {
                    float y = acc[r] + red[r*128 + cl] + bb;
                    g_Y2[(r0+r)*128 + cl] = y;
                    s1 += y; s2 += y*y;
                }
                atomicAdd(&g_stats[512 + cl], s1);
                atomicAdd(&g_stats[640 + cl], s2);
            }
            __syncthreads();
        }
    }
    gbar();

    // ===== Phase 6: out = relu(bn2(Y2)) @ o_w3 + o_b3 ========================
    {
        float* sc = sm;             // [128]
        float* sb = sm + 128;       // [128]
        float* h  = sm + 256;       // [8][128]
        float* w3 = sm + 1280;      // [128*7]
        float* b3 = sm + 2176;      // [7]
        int wid = tid >> 5;
        for (int t = blockIdx.x; t < 80; t += NBLK) {
            int r0 = t * 8;
            if (tid < 128) {
                float m = g_stats[512 + tid] * (1.f/NSEG);
                float v = g_stats[640 + tid] * (1.f/NSEG) - m*m;
                float s = rsqrtf(v + 1e-5f) * bn2g[tid];
                sc[tid] = s; sb[tid] = bn2b[tid] - m*s;
            }
            for (int idx = tid; idx < 128*7; idx += 256) w3[idx] = ow3[idx];
            if (tid < 7) b3[tid] = ob3[tid];
            __syncthreads();
            for (int idx = tid; idx < 8*128; idx += 256) {
                int r = idx >> 7, j = idx & 127;
                float y = g_Y2[(r0+r)*128 + j];
                h[r*128 + j] = fmaxf(fmaf(y, sc[j], sb[j]), 0.f);
            }
            __syncthreads();
            float hv[4];
            #pragma unroll
            for (int u = 0; u < 4; u++) hv[u] = h[wid*128 + lane + u*32];
            #pragma unroll
            for (int j = 0; j < 7; j++) {
                float a = 0.f;
                #pragma unroll
                for (int u = 0; u < 4; u++) a = fmaf(hv[u], w3[(lane + u*32)*7 + j], a);
                #pragma unroll
                for (int o = 16; o; o >>= 1) a += __shfl_down_sync(0xffffffffu, a, o);
                if (lane == 0) out[(r0+wid)*7 + j] = a + b3[j];
            }
            __syncthreads();
        }
    }
}

// ---------------------------------------------------------------------------
extern "C" void kernel_launch(void* const* d_in, const int* in_sizes, int n_in,
                              void* d_out, int out_size)
{
    const float* noise = (const float*)d_in[0];
    const int*   ts    = (const int*)  d_in[1];
    const float* pcs   = (const float*)d_in[2];
    const int*   blen  = (const int*)  d_in[4];
    const float* pew   = (const float*)d_in[5];
    const float* peb   = (const float*)d_in[6];
    const float* tw1   = (const float*)d_in[7];
    const float* tb1   = (const float*)d_in[8];
    const float* tw2   = (const float*)d_in[9];
    const float* tb2   = (const float*)d_in[10];
    const float* pfw   = (const float*)d_in[11];
    const float* pfb   = (const float*)d_in[12];
    const float* ow1   = (const float*)d_in[13];
    const float* ob1   = (const float*)d_in[14];
    const float* bn1g  = (const float*)d_in[15];
    const float* bn1b  = (const float*)d_in[16];
    const float* ow2   = (const float*)d_in[17];
    const float* ob2   = (const float*)d_in[18];
    const float* bn2g  = (const float*)d_in[19];
    const float* bn2b  = (const float*)d_in[20];
    const float* ow3   = (const float*)d_in[21];
    const float* ob3   = (const float*)d_in[22];
    float* out = (float*)d_out;

    mega<<<NBLK, 256>>>(noise, ts, pcs, blen, pew, peb,
                        tw1, tb1, tw2, tb2, pfw, pfb,
                        ow1, ob1, bn1g, bn1b,
                        ow2, ob2, bn2g, bn2b,
                        ow3, ob3, out);
}